// round 2
// baseline (speedup 1.0000x reference)
#include <cuda_runtime.h>

#define D_IN    128
#define D_MAIN  256
#define D_BLOCK 512
#define N_CAND  100000
#define BATCH   1024
#define CTX     96
#define NROWS_T (BATCH * CTX)

// ---------------------------------------------------------------------------
// Scratch (static __device__ — no allocations allowed)
// ---------------------------------------------------------------------------
__device__ float g_h1[N_CAND * D_MAIN];      // candidates: lin out
__device__ float g_u [N_CAND * D_BLOCK];     // candidates: block0 hidden
__device__ float g_x2[N_CAND * D_MAIN];      // candidates: residual out
__device__ float g_ln[N_CAND * D_MAIN];      // candidates: mixer LN
__device__ float g_ck[N_CAND * D_MAIN];      // candidate_k
__device__ float g_cknorm[N_CAND];           // ||candidate_k||^2
__device__ float g_S[BATCH * N_CAND];        // scores 2*k.ck - ||ck||^2

__device__ int   g_idx[BATCH * CTX];
__device__ float g_sv [BATCH * CTX];
__device__ float g_probs[BATCH * CTX];
__device__ float g_y  [NROWS_T];
__device__ float g_diff[NROWS_T * D_MAIN];
__device__ float g_t1 [NROWS_T * D_BLOCK];
__device__ float g_val[NROWS_T * D_MAIN];

__device__ float g_bh1[BATCH * D_MAIN];
__device__ float g_bu [BATCH * D_BLOCK];
__device__ float g_bx2[BATCH * D_MAIN];
__device__ float g_bln[BATCH * D_MAIN];
__device__ float g_bk [BATCH * D_MAIN];
__device__ float g_x3 [BATCH * D_MAIN];
__device__ float g_ln2[BATCH * D_MAIN];
__device__ float g_pt [BATCH * D_BLOCK];
__device__ float g_x4 [BATCH * D_MAIN];

// ---------------------------------------------------------------------------
// Generic fp32 tiled GEMM: C[M,N] = A[M,K] @ B  (B is [K,N] or, if TB, [N,K])
// 128x128 block tile, BK=16, 8x8 per thread, 256 threads.
// Epilogue flags compose: score(2x - vec[n]) -> bias -> relu -> resid -> ylab
// ---------------------------------------------------------------------------
enum { EPI_BIAS = 1, EPI_RELU = 2, EPI_RESID = 4, EPI_YLAB = 8, EPI_SCORE = 16 };

template <int EPI, bool TB>
__global__ __launch_bounds__(256)
void gemm_k(const float* __restrict__ A, const float* __restrict__ B,
            float* __restrict__ C, int M, int N, int K,
            const float* __restrict__ bias, const float* __restrict__ resid,
            const float* __restrict__ rowscale, const float* __restrict__ vec)
{
    __shared__ float As[16][132];
    __shared__ float Bs[16][132];

    const int tid  = threadIdx.x;
    const int tcol = tid & 15;
    const int trow = tid >> 4;
    const int m0 = blockIdx.y * 128;
    const int n0 = blockIdx.x * 128;

    float acc[8][8];
#pragma unroll
    for (int i = 0; i < 8; i++)
#pragma unroll
        for (int j = 0; j < 8; j++) acc[i][j] = 0.f;

    const int aRow = tid >> 2;           // 0..63
    const int aCol = (tid & 3) * 4;      // 0,4,8,12

    for (int k0 = 0; k0 < K; k0 += 16) {
        // ---- load A tile (BMxBK), store transposed As[k][m]
#pragma unroll
        for (int r = 0; r < 128; r += 64) {
            int m = m0 + aRow + r;
            float4 v = make_float4(0.f, 0.f, 0.f, 0.f);
            if (m < M) v = *(const float4*)(A + (size_t)m * K + k0 + aCol);
            As[aCol + 0][aRow + r] = v.x;
            As[aCol + 1][aRow + r] = v.y;
            As[aCol + 2][aRow + r] = v.z;
            As[aCol + 3][aRow + r] = v.w;
        }
        // ---- load B tile
        if (!TB) {
#pragma unroll
            for (int r = 0; r < 16; r += 8) {
                int kk = (tid >> 5) + r;
                int nc = (tid & 31) * 4;
                int n  = n0 + nc;
                float4 v = make_float4(0.f, 0.f, 0.f, 0.f);
                if (n < N) v = *(const float4*)(B + (size_t)(k0 + kk) * N + n);
                *(float4*)&Bs[kk][nc] = v;
            }
        } else {
#pragma unroll
            for (int r = 0; r < 128; r += 64) {
                int nr = (tid >> 2) + r;
                int n  = n0 + nr;
                int kk = (tid & 3) * 4;
                float4 v = make_float4(0.f, 0.f, 0.f, 0.f);
                if (n < N) v = *(const float4*)(B + (size_t)n * K + k0 + kk);
                Bs[kk + 0][nr] = v.x;
                Bs[kk + 1][nr] = v.y;
                Bs[kk + 2][nr] = v.z;
                Bs[kk + 3][nr] = v.w;
            }
        }
        __syncthreads();

#pragma unroll
        for (int kk = 0; kk < 16; kk++) {
            float a[8], b[8];
            *(float4*)&a[0] = *(const float4*)&As[kk][trow * 8];
            *(float4*)&a[4] = *(const float4*)&As[kk][trow * 8 + 4];
            *(float4*)&b[0] = *(const float4*)&Bs[kk][tcol * 8];
            *(float4*)&b[4] = *(const float4*)&Bs[kk][tcol * 8 + 4];
#pragma unroll
            for (int i = 0; i < 8; i++)
#pragma unroll
                for (int j = 0; j < 8; j++) acc[i][j] = fmaf(a[i], b[j], acc[i][j]);
        }
        __syncthreads();
    }

#pragma unroll
    for (int i = 0; i < 8; i++) {
        int m = m0 + trow * 8 + i;
        if (m >= M) continue;
#pragma unroll
        for (int j = 0; j < 8; j++) {
            int n = n0 + tcol * 8 + j;
            if (n >= N) continue;
            float v = acc[i][j];
            if (EPI & EPI_SCORE) v = 2.f * v - vec[n];
            if (EPI & EPI_BIAS)  v += bias[n];
            if (EPI & EPI_RELU)  v = fmaxf(v, 0.f);
            if (EPI & EPI_RESID) v += resid[(size_t)m * N + n];
            if (EPI & EPI_YLAB)  v += rowscale[m] * vec[n] + bias[n];
            C[(size_t)m * N + n] = v;
        }
    }
}

template <int EPI, bool TB>
static inline void gemm(const float* A, const float* B, float* C,
                        int M, int N, int K,
                        const float* bias = nullptr, const float* resid = nullptr,
                        const float* rowscale = nullptr, const float* vec = nullptr)
{
    dim3 grid((N + 127) / 128, (M + 127) / 128);
    gemm_k<EPI, TB><<<grid, 256>>>(A, B, C, M, N, K, bias, resid, rowscale, vec);
}

// ---------------------------------------------------------------------------
// Block helpers (256 threads)
// ---------------------------------------------------------------------------
__device__ __forceinline__ float blk_sum256(float v, float* sh)
{
    int t = threadIdx.x;
#pragma unroll
    for (int o = 16; o; o >>= 1) v += __shfl_down_sync(0xFFFFFFFFu, v, o);
    if ((t & 31) == 0) sh[t >> 5] = v;
    __syncthreads();
    float tot = 0.f;
#pragma unroll
    for (int i = 0; i < 8; i++) tot += sh[i];
    __syncthreads();
    return tot;
}

// LayerNorm over rows of width 256. grid = rows, block = 256.
__global__ __launch_bounds__(256)
void ln_kernel(const float* __restrict__ X, const float* __restrict__ g,
               const float* __restrict__ b, float* __restrict__ Y)
{
    __shared__ float sh[8];
    int row = blockIdx.x, t = threadIdx.x;
    float v = X[(size_t)row * D_MAIN + t];
    float s  = blk_sum256(v, sh);
    float ss = blk_sum256(v * v, sh);
    float mean = s * (1.f / 256.f);
    float var  = ss * (1.f / 256.f) - mean * mean;
    float rs = rsqrtf(var + 1e-5f);
    Y[(size_t)row * D_MAIN + t] = (v - mean) * rs * g[t] + b[t];
}

// ||row||^2 for D_MAIN-wide rows; 8 rows per 256-thread block (1 warp/row).
__global__ __launch_bounds__(256)
void rownorm_kernel(const float* __restrict__ X, float* __restrict__ nrm, int M)
{
    int row = blockIdx.x * 8 + (threadIdx.x >> 5);
    if (row >= M) return;
    int lane = threadIdx.x & 31;
    const float* xr = X + (size_t)row * D_MAIN;
    float s = 0.f;
#pragma unroll
    for (int i = 0; i < 8; i++) { float t = xr[lane + i * 32]; s = fmaf(t, t, s); }
#pragma unroll
    for (int o = 16; o; o >>= 1) s += __shfl_down_sync(0xFFFFFFFFu, s, o);
    if (lane == 0) nrm[row] = s;
}

// ---------------------------------------------------------------------------
// Exact top-96 per row via 4-level (8-bit) radix select on orderable uint key.
// Ties taken by smallest index (matches jax.lax.top_k).
// ---------------------------------------------------------------------------
__global__ __launch_bounds__(256)
void topk_kernel(const float* __restrict__ S, int* __restrict__ idxOut,
                 float* __restrict__ valOut)
{
    int b = blockIdx.x;
    const float* row = S + (size_t)b * N_CAND;
    __shared__ int hist[256];
    __shared__ unsigned sh_prefix;
    __shared__ int sh_need, sh_cnt, sh_tie;
    __shared__ int tieIdx[512];
    int tid = threadIdx.x;
    if (tid == 0) { sh_prefix = 0u; sh_need = CTX; }

    for (int lvl = 0; lvl < 4; lvl++) {
        hist[tid] = 0;
        __syncthreads();
        unsigned pre = sh_prefix;
        int need = sh_need;
        int resolved = 8 * lvl;
        unsigned maskhi = resolved ? (0xFFFFFFFFu << (32 - resolved)) : 0u;
        int shift = 24 - resolved;
        for (int i = tid; i < N_CAND; i += 256) {
            unsigned u = __float_as_uint(row[i]);
            u = (u & 0x80000000u) ? ~u : (u | 0x80000000u);
            if ((u & maskhi) == pre) atomicAdd(&hist[(u >> shift) & 255], 1);
        }
        __syncthreads();
        if (tid == 0) {
            int cum = 0;
            for (int bin = 255; bin >= 0; bin--) {
                int h = hist[bin];
                if (cum + h >= need) {
                    sh_need = need - cum;
                    sh_prefix = pre | ((unsigned)bin << shift);
                    break;
                }
                cum += h;
            }
        }
        __syncthreads();
    }
    unsigned thr = sh_prefix;
    int need = sh_need;
    if (tid == 0) { sh_cnt = 0; sh_tie = 0; }
    __syncthreads();
    for (int i = tid; i < N_CAND; i += 256) {
        float f = row[i];
        unsigned u = __float_as_uint(f);
        u = (u & 0x80000000u) ? ~u : (u | 0x80000000u);
        if (u > thr) {
            int p = atomicAdd(&sh_cnt, 1);
            idxOut[b * CTX + p] = i;
            valOut[b * CTX + p] = f;
        } else if (u == thr) {
            int p = atomicAdd(&sh_tie, 1);
            if (p < 512) tieIdx[p] = i;
        }
    }
    __syncthreads();
    if (tid == 0) {
        int base = sh_cnt;
        int tn = sh_tie < 512 ? sh_tie : 512;
        for (int s = 0; s < need; s++) {
            int best = 0x7FFFFFFF, bi = 0;
            for (int j = 0; j < tn; j++) {
                int v = tieIdx[j];
                if (v < best) { best = v; bi = j; }
            }
            tieIdx[bi] = 0x7FFFFFFF;
            idxOut[b * CTX + base + s] = best;
            valOut[b * CTX + base + s] = row[best];
        }
    }
}

// softmax over 96 scores per row (per-row constant offset cancels).
__global__ __launch_bounds__(128)
void softmax96(const float* __restrict__ sv, float* __restrict__ probs)
{
    __shared__ float sh[128];
    int b = blockIdx.x, t = threadIdx.x;
    float v = (t < CTX) ? sv[b * CTX + t] : -1e30f;
    sh[t] = v;
    __syncthreads();
#pragma unroll
    for (int o = 64; o; o >>= 1) { if (t < o) sh[t] = fmaxf(sh[t], sh[t + o]); __syncthreads(); }
    float mx = sh[0];
    __syncthreads();
    float e = (t < CTX) ? expf(v - mx) : 0.f;
    sh[t] = e;
    __syncthreads();
#pragma unroll
    for (int o = 64; o; o >>= 1) { if (t < o) sh[t] += sh[t + o]; __syncthreads(); }
    float inv = 1.f / sh[0];
    if (t < CTX) probs[b * CTX + t] = e * inv;
}

// diff rows (k_b - ck_idx), plus y gather. grid = NROWS_T, block = 256.
__global__ __launch_bounds__(256)
void build_diff(const int* __restrict__ idx, const float* __restrict__ bk,
                const float* __restrict__ ck, const float* __restrict__ cy,
                float* __restrict__ diff, float* __restrict__ yrow)
{
    int r = blockIdx.x, t = threadIdx.x;
    int b = r / CTX;
    int id = idx[r];
    diff[(size_t)r * D_MAIN + t] = bk[b * D_MAIN + t] - ck[(size_t)id * D_MAIN + t];
    if (t == 0) yrow[r] = cy[id];
}

// context aggregation: x3 = bx2 + sum_c probs * val
__global__ __launch_bounds__(256)
void reduce_ctx(const float* __restrict__ probs, const float* __restrict__ val,
                const float* __restrict__ bx2, float* __restrict__ x3)
{
    __shared__ float p[CTX];
    int b = blockIdx.x, d = threadIdx.x;
    if (d < CTX) p[d] = probs[b * CTX + d];
    __syncthreads();
    float acc = bx2[b * D_MAIN + d];
    const float* vb = val + (size_t)b * CTX * D_MAIN;
#pragma unroll 4
    for (int c = 0; c < CTX; c++) acc = fmaf(p[c], vb[c * D_MAIN + d], acc);
    x3[b * D_MAIN + d] = acc;
}

// head: out = relu(LN(x)) @ h_w + h_b2
__global__ __launch_bounds__(256)
void head_kernel(const float* __restrict__ X, const float* __restrict__ hg,
                 const float* __restrict__ hb, const float* __restrict__ hw,
                 const float* __restrict__ hb2, float* __restrict__ out)
{
    __shared__ float sh[8];
    int b = blockIdx.x, t = threadIdx.x;
    float v = X[(size_t)b * D_MAIN + t];
    float s  = blk_sum256(v, sh);
    float ss = blk_sum256(v * v, sh);
    float mean = s * (1.f / 256.f);
    float var  = ss * (1.f / 256.f) - mean * mean;
    float rs = rsqrtf(var + 1e-5f);
    float y = fmaxf((v - mean) * rs * hg[t] + hb[t], 0.f);
    float p = blk_sum256(y * hw[t], sh);
    if (t == 0) out[b] = p + hb2[0];
}

// ---------------------------------------------------------------------------
// Launch
// ---------------------------------------------------------------------------
template <typename T>
static inline T* sym(const void* s)
{
    void* p = nullptr;
    cudaGetSymbolAddress(&p, (const void*)s);
    return (T*)p;
}

extern "C" void kernel_launch(void* const* d_in, const int* in_sizes, int n_in,
                              void* d_out, int out_size)
{
    // Input order detection: dict order puts context_size (1 elem) at index 3;
    // signature order puts lin_w (32768 elems) there.
    int wb = (in_sizes[3] == 1) ? 4 : 3;

    const float* x_num  = (const float*)d_in[0];
    const float* cand_x = (const float*)d_in[1];
    const float* cand_y = (const float*)d_in[2];
    const float* lin_w = (const float*)d_in[wb + 0];
    const float* lin_b = (const float*)d_in[wb + 1];
    const float* b0_w1 = (const float*)d_in[wb + 2];
    const float* b0_b1 = (const float*)d_in[wb + 3];
    const float* b0_w2 = (const float*)d_in[wb + 4];
    const float* b0_b2 = (const float*)d_in[wb + 5];
    const float* mix_g = (const float*)d_in[wb + 6];
    const float* mix_b = (const float*)d_in[wb + 7];
    const float* K_w   = (const float*)d_in[wb + 8];
    const float* K_b   = (const float*)d_in[wb + 9];
    const float* lab_w = (const float*)d_in[wb + 10];
    const float* lab_b = (const float*)d_in[wb + 11];
    const float* T_w1  = (const float*)d_in[wb + 12];
    const float* T_b1  = (const float*)d_in[wb + 13];
    const float* T_w2  = (const float*)d_in[wb + 14];
    const float* p_g   = (const float*)d_in[wb + 15];
    const float* p_b   = (const float*)d_in[wb + 16];
    const float* p_w1  = (const float*)d_in[wb + 17];
    const float* p_b1  = (const float*)d_in[wb + 18];
    const float* p_w2  = (const float*)d_in[wb + 19];
    const float* p_b2  = (const float*)d_in[wb + 20];
    const float* h_g   = (const float*)d_in[wb + 21];
    const float* h_b   = (const float*)d_in[wb + 22];
    const float* h_w   = (const float*)d_in[wb + 23];
    const float* h_b2  = (const float*)d_in[wb + 24];

    float* p_h1  = sym<float>(&g_h1);
    float* p_u   = sym<float>(&g_u);
    float* p_x2  = sym<float>(&g_x2);
    float* p_ln  = sym<float>(&g_ln);
    float* p_ck  = sym<float>(&g_ck);
    float* p_ckn = sym<float>(&g_cknorm);
    float* p_S   = sym<float>(&g_S);
    int*   p_idx = sym<int>(&g_idx);
    float* p_sv  = sym<float>(&g_sv);
    float* p_pr  = sym<float>(&g_probs);
    float* p_y   = sym<float>(&g_y);
    float* p_df  = sym<float>(&g_diff);
    float* p_t1  = sym<float>(&g_t1);
    float* p_val = sym<float>(&g_val);
    float* p_bh1 = sym<float>(&g_bh1);
    float* p_bu  = sym<float>(&g_bu);
    float* p_bx2 = sym<float>(&g_bx2);
    float* p_bln = sym<float>(&g_bln);
    float* p_bk  = sym<float>(&g_bk);
    float* p_x3  = sym<float>(&g_x3);
    float* p_ln2 = sym<float>(&g_ln2);
    float* p_pt  = sym<float>(&g_pt);
    float* p_x4  = sym<float>(&g_x4);

    // ---- candidate encode chain ----
    gemm<EPI_BIAS, false>(cand_x, lin_w, p_h1, N_CAND, D_MAIN, D_IN, lin_b);
    gemm<EPI_BIAS | EPI_RELU, false>(p_h1, b0_w1, p_u, N_CAND, D_BLOCK, D_MAIN, b0_b1);
    gemm<EPI_BIAS | EPI_RESID, false>(p_u, b0_w2, p_x2, N_CAND, D_MAIN, D_BLOCK, b0_b2, p_h1);
    ln_kernel<<<N_CAND, 256>>>(p_x2, mix_g, mix_b, p_ln);
    gemm<EPI_BIAS, false>(p_ln, K_w, p_ck, N_CAND, D_MAIN, D_MAIN, K_b);
    rownorm_kernel<<<(N_CAND + 7) / 8, 256>>>(p_ck, p_ckn, N_CAND);

    // ---- batch encode chain ----
    gemm<EPI_BIAS, false>(x_num, lin_w, p_bh1, BATCH, D_MAIN, D_IN, lin_b);
    gemm<EPI_BIAS | EPI_RELU, false>(p_bh1, b0_w1, p_bu, BATCH, D_BLOCK, D_MAIN, b0_b1);
    gemm<EPI_BIAS | EPI_RESID, false>(p_bu, b0_w2, p_bx2, BATCH, D_MAIN, D_BLOCK, b0_b2, p_bh1);
    ln_kernel<<<BATCH, 256>>>(p_bx2, mix_g, mix_b, p_bln);
    gemm<EPI_BIAS, false>(p_bln, K_w, p_bk, BATCH, D_MAIN, D_MAIN, K_b);

    // ---- KNN scores + selection ----
    gemm<EPI_SCORE, true>(p_bk, p_ck, p_S, BATCH, N_CAND, D_MAIN,
                          nullptr, nullptr, nullptr, p_ckn);
    topk_kernel<<<BATCH, 256>>>(p_S, p_idx, p_sv);
    softmax96<<<BATCH, 128>>>(p_sv, p_pr);

    // ---- context values ----
    build_diff<<<NROWS_T, 256>>>(p_idx, p_bk, p_ck, cand_y, p_df, p_y);
    gemm<EPI_BIAS | EPI_RELU, false>(p_df, T_w1, p_t1, NROWS_T, D_BLOCK, D_MAIN, T_b1);
    gemm<EPI_YLAB, false>(p_t1, T_w2, p_val, NROWS_T, D_MAIN, D_BLOCK,
                          lab_b, nullptr, p_y, lab_w);
    reduce_ctx<<<BATCH, 256>>>(p_pr, p_val, p_bx2, p_x3);

    // ---- tail MLP + head ----
    ln_kernel<<<BATCH, 256>>>(p_x3, p_g, p_b, p_ln2);
    gemm<EPI_BIAS | EPI_RELU, false>(p_ln2, p_w1, p_pt, BATCH, D_BLOCK, D_MAIN, p_b1);
    gemm<EPI_BIAS | EPI_RESID, false>(p_pt, p_w2, p_x4, BATCH, D_MAIN, D_BLOCK, p_b2, p_x3);
    head_kernel<<<BATCH, 256>>>(p_x4, h_g, h_b, h_w, h_b2, (float*)d_out);
}

// round 3
// speedup vs baseline: 1.0479x; 1.0479x over previous
#include <cuda_runtime.h>

#define D_IN    128
#define D_MAIN  256
#define D_BLOCK 512
#define N_CAND  100000
#define BATCH   1024
#define CTX     96
#define NROWS_T (BATCH * CTX)

// ---------------------------------------------------------------------------
// Scratch (static __device__ — no allocations allowed)
// ---------------------------------------------------------------------------
__device__ float g_h1[N_CAND * D_MAIN];      // candidates: lin out
__device__ float g_u [N_CAND * D_BLOCK];     // candidates: block0 hidden
__device__ float g_x2[N_CAND * D_MAIN];      // candidates: residual out
__device__ float g_ln[N_CAND * D_MAIN];      // candidates: mixer LN
__device__ float g_ck[N_CAND * D_MAIN];      // candidate_k
__device__ float g_cknorm[N_CAND];           // ||candidate_k||^2
__device__ float g_S[BATCH * N_CAND];        // scores 2*k.ck - ||ck||^2

__device__ int   g_idx[BATCH * CTX];
__device__ float g_sv [BATCH * CTX];
__device__ float g_probs[BATCH * CTX];
__device__ float g_y  [NROWS_T];
__device__ float g_diff[NROWS_T * D_MAIN];
__device__ float g_t1 [NROWS_T * D_BLOCK];
__device__ float g_val[NROWS_T * D_MAIN];

__device__ float g_bh1[BATCH * D_MAIN];
__device__ float g_bu [BATCH * D_BLOCK];
__device__ float g_bx2[BATCH * D_MAIN];
__device__ float g_bln[BATCH * D_MAIN];
__device__ float g_bk [BATCH * D_MAIN];
__device__ float g_x3 [BATCH * D_MAIN];
__device__ float g_ln2[BATCH * D_MAIN];
__device__ float g_pt [BATCH * D_BLOCK];
__device__ float g_x4 [BATCH * D_MAIN];

// ---------------------------------------------------------------------------
// Packed f32x2 helpers (Blackwell FFMA2 — not emitted by ptxas from C++)
// ---------------------------------------------------------------------------
__device__ __forceinline__ unsigned long long pk2(float x, float y)
{
    unsigned long long r;
    asm("mov.b64 %0, {%1, %2};" : "=l"(r) : "f"(x), "f"(y));
    return r;
}
__device__ __forceinline__ void fma2(unsigned long long& d,
                                     unsigned long long a, unsigned long long b)
{
    asm("fma.rn.f32x2 %0, %1, %2, %0;" : "+l"(d) : "l"(a), "l"(b));
}
__device__ __forceinline__ void upk2(unsigned long long v, float& x, float& y)
{
    asm("mov.b64 {%0, %1}, %2;" : "=f"(x), "=f"(y) : "l"(v));
}

// ---------------------------------------------------------------------------
// Generic fp32 tiled GEMM: C[M,N] = A[M,K] @ B  (B is [K,N] or, if TB, [N,K])
// 128x128 block tile, BK=16, 8x8 per thread (packed f32x2 accum), 256 threads.
// Epilogue flags compose: score(2x - vec[n]) -> bias -> relu -> resid -> ylab
// ---------------------------------------------------------------------------
enum { EPI_BIAS = 1, EPI_RELU = 2, EPI_RESID = 4, EPI_YLAB = 8, EPI_SCORE = 16 };

template <int EPI, bool TB>
__global__ __launch_bounds__(256, 2)
void gemm_k(const float* __restrict__ A, const float* __restrict__ B,
            float* __restrict__ C, int M, int N, int K,
            const float* __restrict__ bias, const float* __restrict__ resid,
            const float* __restrict__ rowscale, const float* __restrict__ vec)
{
    __shared__ __align__(16) float As[16][132];
    __shared__ __align__(16) float Bs[16][132];

    const int tid  = threadIdx.x;
    const int tcol = tid & 15;
    const int trow = tid >> 4;
    const int m0 = blockIdx.y * 128;
    const int n0 = blockIdx.x * 128;

    unsigned long long acc2[8][4];
#pragma unroll
    for (int i = 0; i < 8; i++)
#pragma unroll
        for (int j = 0; j < 4; j++) acc2[i][j] = 0ull;

    const int aRow = tid >> 2;           // 0..63
    const int aCol = (tid & 3) * 4;      // 0,4,8,12

    for (int k0 = 0; k0 < K; k0 += 16) {
        // ---- load A tile (BMxBK), store transposed As[k][m]
#pragma unroll
        for (int r = 0; r < 128; r += 64) {
            int m = m0 + aRow + r;
            float4 v = make_float4(0.f, 0.f, 0.f, 0.f);
            if (m < M) v = *(const float4*)(A + (size_t)m * K + k0 + aCol);
            As[aCol + 0][aRow + r] = v.x;
            As[aCol + 1][aRow + r] = v.y;
            As[aCol + 2][aRow + r] = v.z;
            As[aCol + 3][aRow + r] = v.w;
        }
        // ---- load B tile
        if (!TB) {
#pragma unroll
            for (int r = 0; r < 16; r += 8) {
                int kk = (tid >> 5) + r;
                int nc = (tid & 31) * 4;
                int n  = n0 + nc;
                float4 v = make_float4(0.f, 0.f, 0.f, 0.f);
                if (n < N) v = *(const float4*)(B + (size_t)(k0 + kk) * N + n);
                *(float4*)&Bs[kk][nc] = v;
            }
        } else {
#pragma unroll
            for (int r = 0; r < 128; r += 64) {
                int nr = (tid >> 2) + r;
                int n  = n0 + nr;
                int kk = (tid & 3) * 4;
                float4 v = make_float4(0.f, 0.f, 0.f, 0.f);
                if (n < N) v = *(const float4*)(B + (size_t)n * K + k0 + kk);
                Bs[kk + 0][nr] = v.x;
                Bs[kk + 1][nr] = v.y;
                Bs[kk + 2][nr] = v.z;
                Bs[kk + 3][nr] = v.w;
            }
        }
        __syncthreads();

#pragma unroll
        for (int kk = 0; kk < 16; kk++) {
            float a[8];
            *(float4*)&a[0] = *(const float4*)&As[kk][trow * 8];
            *(float4*)&a[4] = *(const float4*)&As[kk][trow * 8 + 4];
            unsigned long long b2[4];
            const unsigned long long* bp =
                (const unsigned long long*)&Bs[kk][tcol * 8];
#pragma unroll
            for (int j = 0; j < 4; j++) b2[j] = bp[j];
            unsigned long long a2[8];
#pragma unroll
            for (int i = 0; i < 8; i++) a2[i] = pk2(a[i], a[i]);
#pragma unroll
            for (int i = 0; i < 8; i++)
#pragma unroll
                for (int j = 0; j < 4; j++) fma2(acc2[i][j], a2[i], b2[j]);
        }
        __syncthreads();
    }

#pragma unroll
    for (int i = 0; i < 8; i++) {
        int m = m0 + trow * 8 + i;
        if (m >= M) continue;
        float accf[8];
#pragma unroll
        for (int j = 0; j < 4; j++) upk2(acc2[i][j], accf[2 * j], accf[2 * j + 1]);
#pragma unroll
        for (int j = 0; j < 8; j++) {
            int n = n0 + tcol * 8 + j;
            if (n >= N) continue;
            float v = accf[j];
            if (EPI & EPI_SCORE) v = 2.f * v - vec[n];
            if (EPI & EPI_BIAS)  v += bias[n];
            if (EPI & EPI_RELU)  v = fmaxf(v, 0.f);
            if (EPI & EPI_RESID) v += resid[(size_t)m * N + n];
            if (EPI & EPI_YLAB)  v += rowscale[m] * vec[n] + bias[n];
            C[(size_t)m * N + n] = v;
        }
    }
}

template <int EPI, bool TB>
static inline void gemm(const float* A, const float* B, float* C,
                        int M, int N, int K,
                        const float* bias = nullptr, const float* resid = nullptr,
                        const float* rowscale = nullptr, const float* vec = nullptr)
{
    dim3 grid((N + 127) / 128, (M + 127) / 128);
    gemm_k<EPI, TB><<<grid, 256>>>(A, B, C, M, N, K, bias, resid, rowscale, vec);
}

// ---------------------------------------------------------------------------
// Block helpers (256 threads)
// ---------------------------------------------------------------------------
__device__ __forceinline__ float blk_sum256(float v, float* sh)
{
    int t = threadIdx.x;
#pragma unroll
    for (int o = 16; o; o >>= 1) v += __shfl_down_sync(0xFFFFFFFFu, v, o);
    if ((t & 31) == 0) sh[t >> 5] = v;
    __syncthreads();
    float tot = 0.f;
#pragma unroll
    for (int i = 0; i < 8; i++) tot += sh[i];
    __syncthreads();
    return tot;
}

// LayerNorm over rows of width 256. grid = rows, block = 256.
__global__ __launch_bounds__(256)
void ln_kernel(const float* __restrict__ X, const float* __restrict__ g,
               const float* __restrict__ b, float* __restrict__ Y)
{
    __shared__ float sh[8];
    int row = blockIdx.x, t = threadIdx.x;
    float v = X[(size_t)row * D_MAIN + t];
    float s  = blk_sum256(v, sh);
    float ss = blk_sum256(v * v, sh);
    float mean = s * (1.f / 256.f);
    float var  = ss * (1.f / 256.f) - mean * mean;
    float rs = rsqrtf(var + 1e-5f);
    Y[(size_t)row * D_MAIN + t] = (v - mean) * rs * g[t] + b[t];
}

// ||row||^2 for D_MAIN-wide rows; 8 rows per 256-thread block (1 warp/row).
__global__ __launch_bounds__(256)
void rownorm_kernel(const float* __restrict__ X, float* __restrict__ nrm, int M)
{
    int row = blockIdx.x * 8 + (threadIdx.x >> 5);
    if (row >= M) return;
    int lane = threadIdx.x & 31;
    const float* xr = X + (size_t)row * D_MAIN;
    float s = 0.f;
#pragma unroll
    for (int i = 0; i < 8; i++) { float t = xr[lane + i * 32]; s = fmaf(t, t, s); }
#pragma unroll
    for (int o = 16; o; o >>= 1) s += __shfl_down_sync(0xFFFFFFFFu, s, o);
    if (lane == 0) nrm[row] = s;
}

// ---------------------------------------------------------------------------
// Exact top-96 per row via 4-level (8-bit) radix select on orderable uint key.
// Ties taken by smallest index (matches jax.lax.top_k).
// ---------------------------------------------------------------------------
__global__ __launch_bounds__(256)
void topk_kernel(const float* __restrict__ S, int* __restrict__ idxOut,
                 float* __restrict__ valOut)
{
    int b = blockIdx.x;
    const float* row = S + (size_t)b * N_CAND;
    __shared__ int hist[256];
    __shared__ unsigned sh_prefix;
    __shared__ int sh_need, sh_cnt, sh_tie;
    __shared__ int tieIdx[512];
    int tid = threadIdx.x;
    if (tid == 0) { sh_prefix = 0u; sh_need = CTX; }

    for (int lvl = 0; lvl < 4; lvl++) {
        hist[tid] = 0;
        __syncthreads();
        unsigned pre = sh_prefix;
        int need = sh_need;
        int resolved = 8 * lvl;
        unsigned maskhi = resolved ? (0xFFFFFFFFu << (32 - resolved)) : 0u;
        int shift = 24 - resolved;
        for (int i = tid; i < N_CAND; i += 256) {
            unsigned u = __float_as_uint(row[i]);
            u = (u & 0x80000000u) ? ~u : (u | 0x80000000u);
            if ((u & maskhi) == pre) atomicAdd(&hist[(u >> shift) & 255], 1);
        }
        __syncthreads();
        if (tid == 0) {
            int cum = 0;
            for (int bin = 255; bin >= 0; bin--) {
                int h = hist[bin];
                if (cum + h >= need) {
                    sh_need = need - cum;
                    sh_prefix = pre | ((unsigned)bin << shift);
                    break;
                }
                cum += h;
            }
        }
        __syncthreads();
    }
    unsigned thr = sh_prefix;
    int need = sh_need;
    if (tid == 0) { sh_cnt = 0; sh_tie = 0; }
    __syncthreads();
    for (int i = tid; i < N_CAND; i += 256) {
        float f = row[i];
        unsigned u = __float_as_uint(f);
        u = (u & 0x80000000u) ? ~u : (u | 0x80000000u);
        if (u > thr) {
            int p = atomicAdd(&sh_cnt, 1);
            idxOut[b * CTX + p] = i;
            valOut[b * CTX + p] = f;
        } else if (u == thr) {
            int p = atomicAdd(&sh_tie, 1);
            if (p < 512) tieIdx[p] = i;
        }
    }
    __syncthreads();
    if (tid == 0) {
        int base = sh_cnt;
        int tn = sh_tie < 512 ? sh_tie : 512;
        for (int s = 0; s < need; s++) {
            int best = 0x7FFFFFFF, bi = 0;
            for (int j = 0; j < tn; j++) {
                int v = tieIdx[j];
                if (v < best) { best = v; bi = j; }
            }
            tieIdx[bi] = 0x7FFFFFFF;
            idxOut[b * CTX + base + s] = best;
            valOut[b * CTX + base + s] = row[best];
        }
    }
}

// softmax over 96 scores per row (per-row constant offset cancels).
__global__ __launch_bounds__(128)
void softmax96(const float* __restrict__ sv, float* __restrict__ probs)
{
    __shared__ float sh[128];
    int b = blockIdx.x, t = threadIdx.x;
    float v = (t < CTX) ? sv[b * CTX + t] : -1e30f;
    sh[t] = v;
    __syncthreads();
#pragma unroll
    for (int o = 64; o; o >>= 1) { if (t < o) sh[t] = fmaxf(sh[t], sh[t + o]); __syncthreads(); }
    float mx = sh[0];
    __syncthreads();
    float e = (t < CTX) ? expf(v - mx) : 0.f;
    sh[t] = e;
    __syncthreads();
#pragma unroll
    for (int o = 64; o; o >>= 1) { if (t < o) sh[t] += sh[t + o]; __syncthreads(); }
    float inv = 1.f / sh[0];
    if (t < CTX) probs[b * CTX + t] = e * inv;
}

// diff rows (k_b - ck_idx), plus y gather. grid = NROWS_T, block = 256.
__global__ __launch_bounds__(256)
void build_diff(const int* __restrict__ idx, const float* __restrict__ bk,
                const float* __restrict__ ck, const float* __restrict__ cy,
                float* __restrict__ diff, float* __restrict__ yrow)
{
    int r = blockIdx.x, t = threadIdx.x;
    int b = r / CTX;
    int id = idx[r];
    diff[(size_t)r * D_MAIN + t] = bk[b * D_MAIN + t] - ck[(size_t)id * D_MAIN + t];
    if (t == 0) yrow[r] = cy[id];
}

// context aggregation: x3 = bx2 + sum_c probs * val
__global__ __launch_bounds__(256)
void reduce_ctx(const float* __restrict__ probs, const float* __restrict__ val,
                const float* __restrict__ bx2, float* __restrict__ x3)
{
    __shared__ float p[CTX];
    int b = blockIdx.x, d = threadIdx.x;
    if (d < CTX) p[d] = probs[b * CTX + d];
    __syncthreads();
    float acc = bx2[b * D_MAIN + d];
    const float* vb = val + (size_t)b * CTX * D_MAIN;
#pragma unroll 4
    for (int c = 0; c < CTX; c++) acc = fmaf(p[c], vb[c * D_MAIN + d], acc);
    x3[b * D_MAIN + d] = acc;
}

// head: out = relu(LN(x)) @ h_w + h_b2
__global__ __launch_bounds__(256)
void head_kernel(const float* __restrict__ X, const float* __restrict__ hg,
                 const float* __restrict__ hb, const float* __restrict__ hw,
                 const float* __restrict__ hb2, float* __restrict__ out)
{
    __shared__ float sh[8];
    int b = blockIdx.x, t = threadIdx.x;
    float v = X[(size_t)b * D_MAIN + t];
    float s  = blk_sum256(v, sh);
    float ss = blk_sum256(v * v, sh);
    float mean = s * (1.f / 256.f);
    float var  = ss * (1.f / 256.f) - mean * mean;
    float rs = rsqrtf(var + 1e-5f);
    float y = fmaxf((v - mean) * rs * hg[t] + hb[t], 0.f);
    float p = blk_sum256(y * hw[t], sh);
    if (t == 0) out[b] = p + hb2[0];
}

// ---------------------------------------------------------------------------
// Launch
// ---------------------------------------------------------------------------
template <typename T>
static inline T* sym(const void* s)
{
    void* p = nullptr;
    cudaGetSymbolAddress(&p, (const void*)s);
    return (T*)p;
}

extern "C" void kernel_launch(void* const* d_in, const int* in_sizes, int n_in,
                              void* d_out, int out_size)
{
    // Input order detection: dict order puts context_size (1 elem) at index 3;
    // signature order puts lin_w (32768 elems) there.
    int wb = (in_sizes[3] == 1) ? 4 : 3;

    const float* x_num  = (const float*)d_in[0];
    const float* cand_x = (const float*)d_in[1];
    const float* cand_y = (const float*)d_in[2];
    const float* lin_w = (const float*)d_in[wb + 0];
    const float* lin_b = (const float*)d_in[wb + 1];
    const float* b0_w1 = (const float*)d_in[wb + 2];
    const float* b0_b1 = (const float*)d_in[wb + 3];
    const float* b0_w2 = (const float*)d_in[wb + 4];
    const float* b0_b2 = (const float*)d_in[wb + 5];
    const float* mix_g = (const float*)d_in[wb + 6];
    const float* mix_b = (const float*)d_in[wb + 7];
    const float* K_w   = (const float*)d_in[wb + 8];
    const float* K_b   = (const float*)d_in[wb + 9];
    const float* lab_w = (const float*)d_in[wb + 10];
    const float* lab_b = (const float*)d_in[wb + 11];
    const float* T_w1  = (const float*)d_in[wb + 12];
    const float* T_b1  = (const float*)d_in[wb + 13];
    const float* T_w2  = (const float*)d_in[wb + 14];
    const float* p_g   = (const float*)d_in[wb + 15];
    const float* p_b   = (const float*)d_in[wb + 16];
    const float* p_w1  = (const float*)d_in[wb + 17];
    const float* p_b1  = (const float*)d_in[wb + 18];
    const float* p_w2  = (const float*)d_in[wb + 19];
    const float* p_b2  = (const float*)d_in[wb + 20];
    const float* h_g   = (const float*)d_in[wb + 21];
    const float* h_b   = (const float*)d_in[wb + 22];
    const float* h_w   = (const float*)d_in[wb + 23];
    const float* h_b2  = (const float*)d_in[wb + 24];

    float* p_h1  = sym<float>(&g_h1);
    float* p_u   = sym<float>(&g_u);
    float* p_x2  = sym<float>(&g_x2);
    float* p_ln  = sym<float>(&g_ln);
    float* p_ck  = sym<float>(&g_ck);
    float* p_ckn = sym<float>(&g_cknorm);
    float* p_S   = sym<float>(&g_S);
    int*   p_idx = sym<int>(&g_idx);
    float* p_sv  = sym<float>(&g_sv);
    float* p_pr  = sym<float>(&g_probs);
    float* p_y   = sym<float>(&g_y);
    float* p_df  = sym<float>(&g_diff);
    float* p_t1  = sym<float>(&g_t1);
    float* p_val = sym<float>(&g_val);
    float* p_bh1 = sym<float>(&g_bh1);
    float* p_bu  = sym<float>(&g_bu);
    float* p_bx2 = sym<float>(&g_bx2);
    float* p_bln = sym<float>(&g_bln);
    float* p_bk  = sym<float>(&g_bk);
    float* p_x3  = sym<float>(&g_x3);
    float* p_ln2 = sym<float>(&g_ln2);
    float* p_pt  = sym<float>(&g_pt);
    float* p_x4  = sym<float>(&g_x4);

    // ---- candidate encode chain ----
    gemm<EPI_BIAS, false>(cand_x, lin_w, p_h1, N_CAND, D_MAIN, D_IN, lin_b);
    gemm<EPI_BIAS | EPI_RELU, false>(p_h1, b0_w1, p_u, N_CAND, D_BLOCK, D_MAIN, b0_b1);
    gemm<EPI_BIAS | EPI_RESID, false>(p_u, b0_w2, p_x2, N_CAND, D_MAIN, D_BLOCK, b0_b2, p_h1);
    ln_kernel<<<N_CAND, 256>>>(p_x2, mix_g, mix_b, p_ln);
    gemm<EPI_BIAS, false>(p_ln, K_w, p_ck, N_CAND, D_MAIN, D_MAIN, K_b);
    rownorm_kernel<<<(N_CAND + 7) / 8, 256>>>(p_ck, p_ckn, N_CAND);

    // ---- batch encode chain ----
    gemm<EPI_BIAS, false>(x_num, lin_w, p_bh1, BATCH, D_MAIN, D_IN, lin_b);
    gemm<EPI_BIAS | EPI_RELU, false>(p_bh1, b0_w1, p_bu, BATCH, D_BLOCK, D_MAIN, b0_b1);
    gemm<EPI_BIAS | EPI_RESID, false>(p_bu, b0_w2, p_bx2, BATCH, D_MAIN, D_BLOCK, b0_b2, p_bh1);
    ln_kernel<<<BATCH, 256>>>(p_bx2, mix_g, mix_b, p_bln);
    gemm<EPI_BIAS, false>(p_bln, K_w, p_bk, BATCH, D_MAIN, D_MAIN, K_b);

    // ---- KNN scores + selection ----
    gemm<EPI_SCORE, true>(p_bk, p_ck, p_S, BATCH, N_CAND, D_MAIN,
                          nullptr, nullptr, nullptr, p_ckn);
    topk_kernel<<<BATCH, 256>>>(p_S, p_idx, p_sv);
    softmax96<<<BATCH, 128>>>(p_sv, p_pr);

    // ---- context values ----
    build_diff<<<NROWS_T, 256>>>(p_idx, p_bk, p_ck, cand_y, p_df, p_y);
    gemm<EPI_BIAS | EPI_RELU, false>(p_df, T_w1, p_t1, NROWS_T, D_BLOCK, D_MAIN, T_b1);
    gemm<EPI_YLAB, false>(p_t1, T_w2, p_val, NROWS_T, D_MAIN, D_BLOCK,
                          lab_b, nullptr, p_y, lab_w);
    reduce_ctx<<<BATCH, 256>>>(p_pr, p_val, p_bx2, p_x3);

    // ---- tail MLP + head ----
    ln_kernel<<<BATCH, 256>>>(p_x3, p_g, p_b, p_ln2);
    gemm<EPI_BIAS | EPI_RELU, false>(p_ln2, p_w1, p_pt, BATCH, D_BLOCK, D_MAIN, p_b1);
    gemm<EPI_BIAS | EPI_RESID, false>(p_pt, p_w2, p_x4, BATCH, D_MAIN, D_BLOCK, p_b2, p_x3);
    head_kernel<<<BATCH, 256>>>(p_x4, h_g, h_b, h_w, h_b2, (float*)d_out);
}